// round 15
// baseline (speedup 1.0000x reference)
#include <cuda_runtime.h>
#include <cuda_bf16.h>
#include <cuda_fp16.h>
#include <cstdint>

#define B_    2
#define T_    2048
#define C_    2048
#define NH_   16
#define KVH_  4
#define HD_   128
#define QKVD_ 3072
#define BT_   (B_*T_)
#define K_    2048

// ---------------- scratch ----------------
__device__ __half g_xs[(size_t)BT_ * K_];        // x fp16
__device__ __half g_wqkvs[(size_t)QKVD_ * K_];   // w_qkv fp16
__device__ __half g_wprojs[(size_t)C_ * K_];     // w_proj fp16
__device__ __half g_ysh[(size_t)BT_ * K_];       // y fp16 (flash output)
__device__ __half g_qs[(size_t)B_ * NH_ * T_ * HD_];   // q fp16 (pre-scaled)
__device__ __half g_ks[(size_t)B_ * KVH_ * T_ * HD_];  // k fp16
__device__ __half g_vt[(size_t)B_ * KVH_ * HD_ * T_];  // v^T fp16 [d][t]

// ---------------- PTX helpers ----------------
__device__ __forceinline__ uint32_t smem_u32(const void* p) {
    uint32_t a;
    asm("{ .reg .u64 t; cvta.to.shared.u64 t, %1; cvt.u32.u64 %0, t; }" : "=r"(a) : "l"(p));
    return a;
}
__device__ __forceinline__ void cp16(uint32_t saddr, const void* g) {
    asm volatile("cp.async.cg.shared.global [%0], [%1], 16;" :: "r"(saddr), "l"(g) : "memory");
}
__device__ __forceinline__ void cp_commit() { asm volatile("cp.async.commit_group;" ::: "memory"); }
#define CP_WAIT(n) asm volatile("cp.async.wait_group %0;" :: "n"(n) : "memory")

__device__ __forceinline__ void ldm4(uint32_t* r, uint32_t addr) {
    asm volatile("ldmatrix.sync.aligned.m8n8.x4.shared.b16 {%0,%1,%2,%3}, [%4];"
                 : "=r"(r[0]), "=r"(r[1]), "=r"(r[2]), "=r"(r[3]) : "r"(addr));
}
// fp16 mma, fp32 accum
__device__ __forceinline__ void mma16816h(float* c, const uint32_t* a, const uint32_t* b) {
    asm volatile(
        "mma.sync.aligned.m16n8k16.row.col.f32.f16.f16.f32 "
        "{%0,%1,%2,%3}, {%4,%5,%6,%7}, {%8,%9}, {%0,%1,%2,%3};"
        : "+f"(c[0]), "+f"(c[1]), "+f"(c[2]), "+f"(c[3])
        : "r"(a[0]), "r"(a[1]), "r"(a[2]), "r"(a[3]), "r"(b[0]), "r"(b[1]));
}
// pack two fp32 -> f16x2 ('lo' element in low half)
__device__ __forceinline__ uint32_t pack_h2(float lo, float hi) {
    uint32_t r;
    asm("cvt.rn.f16x2.f32 %0, %1, %2;" : "=r"(r) : "f"(hi), "f"(lo));
    return r;
}

// ---------------- merged fp32 -> fp16 conversion (x, w_qkv, w_proj) ----------------
#define CN1 (BT_ * 512)              // x       float4 count
#define CN2 (QKVD_ * 512)            // w_qkv
#define CN3 (C_ * 512)               // w_proj
#define CTOT (CN1 + CN2 + CN3)

__global__ __launch_bounds__(256) void conv_all(
    const float* __restrict__ x, const float* __restrict__ wq,
    const float* __restrict__ wp, __half* __restrict__ ox,
    __half* __restrict__ owq, __half* __restrict__ owp)
{
    int i = blockIdx.x * 256 + threadIdx.x;
    if (i >= CTOT) return;
    const float4* src; uint2* dst; int loc;
    if (i < CN1)            { src = (const float4*)x;  dst = (uint2*)ox;  loc = i; }
    else if (i < CN1 + CN2) { src = (const float4*)wq; dst = (uint2*)owq; loc = i - CN1; }
    else                    { src = (const float4*)wp; dst = (uint2*)owp; loc = i - CN1 - CN2; }
    float4 v = src[loc];
    uint2 o;
    o.x = pack_h2(v.x, v.y);
    o.y = pack_h2(v.z, v.w);
    dst[loc] = o;
}

// ---------------- shared GEMM mainloop config ----------------
// 128x256 CTA / 64x64 warp, K-region = 128, 2 buffers, 1 barrier per region.
#define GPITCH  272
#define GT_A    0
#define GT_B    34816                // 128 * 272
#define GREGION 104448               // 34816 + 256*272
#define NREG    (K_ / 128)           // 16
#define GEMM_SMEM (2 * GREGION)      // 208896

__device__ __forceinline__ void g_load_region(
    uint32_t st, const __half* Ag, const __half* Bg,
    size_t bm, size_t bn, int kc, int tid)
{
#pragma unroll
    for (int j = 0; j < 8; j++) {
        int idx = tid + j * 256;           // 0..2047
        int r = idx >> 4, c = idx & 15;
        cp16(st + GT_A + (uint32_t)r * GPITCH + c * 16, Ag + (bm + r) * K_ + kc + c * 8);
    }
#pragma unroll
    for (int j = 0; j < 16; j++) {
        int idx = tid + j * 256;           // 0..4095
        int r = idx >> 4, c = idx & 15;
        cp16(st + GT_B + (uint32_t)r * GPITCH + c * 16, Bg + (bn + r) * K_ + kc + c * 8);
    }
}

// Mainloop macro body (fills acc[4][8][4]); used by both GEMM kernels.
#define GEMM_MAINLOOP(Ag, Bg)                                                  \
    g_load_region(sb, Ag, Bg, bm, bn, 0, tid);                                 \
    cp_commit();                                                               \
    const int a_row = lane & 15, a_kh = lane >> 4;                             \
    const int b_row = (lane & 7) | ((lane >> 1) & 8);                          \
    const int b_kh = (lane >> 3) & 1;                                          \
    const uint32_t a_base = (uint32_t)(wm + a_row) * GPITCH + a_kh * 16;       \
    const uint32_t b_base = (uint32_t)(wn + b_row) * GPITCH + b_kh * 16;       \
    uint32_t ah[2][4][4], bh[2][4][4];                                         \
    for (int r = 0; r < NREG; r++) {                                           \
        CP_WAIT(0);                                                            \
        __syncthreads();                                                       \
        if (r + 1 < NREG)                                                      \
            g_load_region(sb + ((r + 1) & 1) * GREGION, Ag, Bg, bm, bn,        \
                          (r + 1) * 128, tid);                                 \
        cp_commit();                                                           \
        const uint32_t st = sb + (r & 1) * GREGION;                            \
        _Pragma("unroll")                                                      \
        for (int mt = 0; mt < 4; mt++)                                         \
            ldm4(ah[0][mt], st + GT_A + a_base + mt * (16 * GPITCH));          \
        _Pragma("unroll")                                                      \
        for (int ng = 0; ng < 4; ng++)                                         \
            ldm4(bh[0][ng], st + GT_B + b_base + ng * (16 * GPITCH));          \
        _Pragma("unroll")                                                      \
        for (int ks = 0; ks < 8; ks++) {                                       \
            const int cur = ks & 1, nxt = cur ^ 1;                             \
            if (ks < 7) {                                                      \
                uint32_t ko = (uint32_t)(ks + 1) * 32;                         \
                _Pragma("unroll")                                              \
                for (int mt = 0; mt < 4; mt++)                                 \
                    ldm4(ah[nxt][mt], st + GT_A + a_base + ko + mt * (16 * GPITCH)); \
                _Pragma("unroll")                                              \
                for (int ng = 0; ng < 4; ng++)                                 \
                    ldm4(bh[nxt][ng], st + GT_B + b_base + ko + ng * (16 * GPITCH)); \
            }                                                                  \
            _Pragma("unroll")                                                  \
            for (int ng = 0; ng < 4; ng++)                                     \
                _Pragma("unroll")                                              \
                for (int mt = 0; mt < 4; mt++) {                               \
                    mma16816h(acc[mt][2 * ng],     ah[cur][mt], &bh[cur][ng][0]); \
                    mma16816h(acc[mt][2 * ng + 1], ah[cur][mt], &bh[cur][ng][2]); \
                }                                                              \
        }                                                                      \
    }

// ---------------- fused qkv GEMM + RoPE + RMSNorm + V-transpose ----------------
// grid (12, 32): bx 0-7 -> q heads, 8-9 -> k heads, 10-11 -> v heads.
__global__ __launch_bounds__(256, 1) void gemm_qkv(
    const __half* __restrict__ Ag, const __half* __restrict__ Bg,
    const float* __restrict__ qw, const float* __restrict__ kw,
    const float* __restrict__ fcos, const float* __restrict__ fsin,
    __half* __restrict__ Qs, __half* __restrict__ Ks, __half* __restrict__ VT)
{
    extern __shared__ char sm[];
    const uint32_t sb = smem_u32(sm);
    const int tid = threadIdx.x;
    const int wid = tid >> 5, lane = tid & 31;
    const size_t bm = (size_t)blockIdx.y * 128;
    const size_t bn = (size_t)blockIdx.x * 256;
    const int wm = (wid & 1) * 64;
    const int wn = (wid >> 1) * 64;

    float acc[4][8][4];
#pragma unroll
    for (int i = 0; i < 4; i++)
#pragma unroll
        for (int j = 0; j < 8; j++)
#pragma unroll
            for (int q = 0; q < 4; q++) acc[i][j][q] = 0.f;

    GEMM_MAINLOOP(Ag, Bg)

    // ---------------- fused epilogue ----------------
    const int er = lane >> 2, ec = (lane & 3) * 2;
    const int b = (int)(bm >> 11);
    const int tb = (int)(bm & 2047);
    __syncthreads();        // smem region buffers now free for reuse

    if (bn < 2560) {
        // ---- q or k: RMSNorm sums (RoPE is norm-preserving -> raw sums OK) ----
        const bool isq = (bn < 2048);
        float* sums = (float*)sm;               // [128 rows][2 heads][2 halves]
        const int hl = wn >> 7, hf = (wn >> 6) & 1;
#pragma unroll
        for (int mt = 0; mt < 4; mt++) {
            float s0 = 0.f, s1 = 0.f;
#pragma unroll
            for (int nf = 0; nf < 8; nf++) {
                s0 += acc[mt][nf][0] * acc[mt][nf][0] + acc[mt][nf][1] * acc[mt][nf][1];
                s1 += acc[mt][nf][2] * acc[mt][nf][2] + acc[mt][nf][3] * acc[mt][nf][3];
            }
            s0 += __shfl_xor_sync(0xffffffffu, s0, 1);
            s0 += __shfl_xor_sync(0xffffffffu, s0, 2);
            s1 += __shfl_xor_sync(0xffffffffu, s1, 1);
            s1 += __shfl_xor_sync(0xffffffffu, s1, 2);
            if ((lane & 3) == 0) {
                int r0 = wm + mt * 16 + er;
                sums[r0 * 4 + hl * 2 + hf]       = s0;
                sums[(r0 + 8) * 4 + hl * 2 + hf] = s1;
            }
        }
        __syncthreads();

        const float post = isq ? 0.08838834764831845f : 1.0f;
        const float* w = isq ? qw : kw;
        const int hseg = (int)((bn + wn) >> 7);
        __half* dstbase = isq
            ? Qs + ((size_t)(b * NH_ + hseg)) * T_ * HD_
            : Ks + ((size_t)(b * KVH_ + (hseg - 16))) * T_ * HD_;

#pragma unroll
        for (int mt = 0; mt < 4; mt++) {
            int r0 = wm + mt * 16 + er;
            int t0 = tb + r0, t1 = t0 + 8;
            float tot0 = sums[r0 * 4 + hl * 2] + sums[r0 * 4 + hl * 2 + 1];
            float tot1 = sums[(r0 + 8) * 4 + hl * 2] + sums[(r0 + 8) * 4 + hl * 2 + 1];
            float ri0 = rsqrtf(tot0 * (1.0f / HD_) + 1e-6f) * post;
            float ri1 = rsqrtf(tot1 * (1.0f / HD_) + 1e-6f) * post;
#pragma unroll
            for (int nf = 0; nf < 8; nf++) {
                int colh = (wn + nf * 8 + ec) & 127;
                int i = colh >> 1;
                float cA = fcos[t0 * 64 + i], sA = fsin[t0 * 64 + i];
                float cB = fcos[t1 * 64 + i], sB = fsin[t1 * 64 + i];
                float a0 = acc[mt][nf][0], b0 = acc[mt][nf][1];
                float a1 = acc[mt][nf][2], b1 = acc[mt][nf][3];
                float q0 = a0 * cA - b0 * sA, q1 = a0 * sA + b0 * cA;
                float q2 = a1 * cB - b1 * sB, q3 = a1 * sB + b1 * cB;
                float w0 = w[colh], w1 = w[colh + 1];
                *(uint32_t*)(dstbase + (size_t)t0 * HD_ + colh) =
                    pack_h2(q0 * w0 * ri0, q1 * w1 * ri0);
                *(uint32_t*)(dstbase + (size_t)t1 * HD_ + colh) =
                    pack_h2(q2 * w0 * ri1, q3 * w1 * ri1);
            }
        }
    } else {
        // ---- v: transpose through smem, coalesced VT writes ----
        __half* tile = (__half*)sm;             // [256 d][136 t-pitch]
#pragma unroll
        for (int mt = 0; mt < 4; mt++) {
            int r0 = wm + mt * 16 + er, r1 = r0 + 8;
#pragma unroll
            for (int nf = 0; nf < 8; nf++) {
                int col = wn + nf * 8 + ec;
                tile[col * 136 + r0]       = __float2half(acc[mt][nf][0]);
                tile[(col + 1) * 136 + r0] = __float2half(acc[mt][nf][1]);
                tile[col * 136 + r1]       = __float2half(acc[mt][nf][2]);
                tile[(col + 1) * 136 + r1] = __float2half(acc[mt][nf][3]);
            }
        }
        __syncthreads();
        const int hv0 = (int)((bn - 2560) >> 7);
#pragma unroll
        for (int it = 0; it < 16; it++) {
            int idx = tid + it * 256;           // 0..4095
            int d = idx >> 4, s8 = idx & 15;
            uint4 val = *(const uint4*)&tile[d * 136 + s8 * 8];
            int hv = hv0 + (d >> 7), dd = d & 127;
            *(uint4*)(VT + ((size_t)(b * KVH_ + hv) * HD_ + dd) * T_ + tb + s8 * 8) = val;
        }
    }
}

// ---------------- generic fp16 NT GEMM (proj), fp32 output ----------------
__global__ __launch_bounds__(256, 1) void gemm_mma(
    const __half* __restrict__ Ag, const __half* __restrict__ Bg,
    float* __restrict__ Cm, int N)
{
    extern __shared__ char sm[];
    const uint32_t sb = smem_u32(sm);
    const int tid = threadIdx.x;
    const int wid = tid >> 5, lane = tid & 31;
    const size_t bm = (size_t)blockIdx.y * 128;
    const size_t bn = (size_t)blockIdx.x * 256;
    const int wm = (wid & 1) * 64;
    const int wn = (wid >> 1) * 64;

    float acc[4][8][4];
#pragma unroll
    for (int i = 0; i < 4; i++)
#pragma unroll
        for (int j = 0; j < 8; j++)
#pragma unroll
            for (int q = 0; q < 4; q++) acc[i][j][q] = 0.f;

    GEMM_MAINLOOP(Ag, Bg)

    const int er = lane >> 2, ec = (lane & 3) * 2;
#pragma unroll
    for (int mt = 0; mt < 4; mt++)
#pragma unroll
        for (int nf = 0; nf < 8; nf++) {
            size_t row = bm + wm + mt * 16 + er;
            size_t col = bn + wn + nf * 8 + ec;
            *(float2*)(Cm + row * (size_t)N + col) =
                make_float2(acc[mt][nf][0], acc[mt][nf][1]);
            *(float2*)(Cm + (row + 8) * (size_t)N + col) =
                make_float2(acc[mt][nf][2], acc[mt][nf][3]);
        }
}

// ---------------- flash attention via mma.sync fp16, K-tile = 128 ----------------
#define QPITCH 272        // bytes per 128-fp16 row (256B + 16 pad)
#define SM_Q 0
#define SM_STAGE0 34816
#define OFF_K 0
#define OFF_V 34816
#define KV_STAGE 69632
#define FA_SMEM (34816 + 2 * 69632)   // 174080

__device__ __forceinline__ void fa_load_kv(
    uint32_t st, const __half* Kg, const __half* Vg, int kt, int tid)
{
#pragma unroll
    for (int j = 0; j < 8; j++) {
        int idx = tid + j * 256;            // 0..2047
        int r = idx >> 4, c = idx & 15;
        cp16(st + OFF_K + (uint32_t)r * QPITCH + c * 16,
             Kg + ((size_t)(kt * 128 + r)) * HD_ + c * 8);
        cp16(st + OFF_V + (uint32_t)r * QPITCH + c * 16,
             Vg + (size_t)r * T_ + kt * 128 + c * 8);
    }
}

__global__ __launch_bounds__(256, 1) void flash_mma(
    const __half* __restrict__ Qs, const __half* __restrict__ Ks,
    const __half* __restrict__ VT, __half* __restrict__ Ys)
{
    extern __shared__ char sm[];
    const uint32_t sb = smem_u32(sm);
    const int tid = threadIdx.x, w = tid >> 5, lane = tid & 31;
    // heavy tiles first
    const int qt = gridDim.x - 1 - blockIdx.x;
    const int h = blockIdx.y, b = blockIdx.z;
    const int q0 = qt * 128;
    const int hk = h >> 2;
    const __half* Qg = Qs + ((size_t)(b * NH_ + h) * T_ + q0) * HD_;
    const __half* Kg = Ks + (size_t)(b * KVH_ + hk) * T_ * HD_;
    const __half* Vg = VT + (size_t)(b * KVH_ + hk) * HD_ * T_;

#pragma unroll
    for (int j = 0; j < 8; j++) {
        int idx = tid + j * 256;            // 0..2047
        int r = idx >> 4, c = idx & 15;
        cp16(sb + SM_Q + (uint32_t)r * QPITCH + c * 16, Qg + (size_t)r * HD_ + c * 8);
    }
    fa_load_kv(sb + SM_STAGE0, Kg, Vg, 0, tid);
    cp_commit();

    float O[16][4];
#pragma unroll
    for (int i = 0; i < 16; i++)
#pragma unroll
        for (int j = 0; j < 4; j++) O[i][j] = 0.f;
    float m0 = -1e30f, m1 = -1e30f, l0 = 0.f, l1 = 0.f;

    const int er = lane >> 2, ec2 = (lane & 3) * 2;
    const int a_row = lane & 15, a_kh = lane >> 4;
    const int b_row = (lane & 7) | ((lane >> 1) & 8), b_kh = (lane >> 3) & 1;
    const int row0 = q0 + w * 16 + er;
    const int nkt = qt + 1;

    uint32_t qf[8][4];      // hoisted Q fragments

    for (int kt = 0; kt < nkt; kt++) {
        if (kt + 1 < nkt) {
            fa_load_kv(sb + SM_STAGE0 + ((kt + 1) & 1) * KV_STAGE, Kg, Vg, kt + 1, tid);
            cp_commit();
            CP_WAIT(1);
        } else {
            CP_WAIT(0);
        }
        __syncthreads();

        if (kt == 0) {
#pragma unroll
            for (int ks = 0; ks < 8; ks++) {
                uint32_t qoff = (uint32_t)(w * 16 + a_row) * QPITCH + ks * 32 + a_kh * 16;
                ldm4(qf[ks], sb + SM_Q + qoff);
            }
        }

        const uint32_t st = sb + SM_STAGE0 + (kt & 1) * KV_STAGE;

        // ---- S = Q K^T over 128 k-cols ----
        float s[16][4];
#pragma unroll
        for (int i = 0; i < 16; i++)
#pragma unroll
            for (int j = 0; j < 4; j++) s[i][j] = 0.f;
#pragma unroll
        for (int ks = 0; ks < 8; ks++) {
#pragma unroll
            for (int ng = 0; ng < 8; ng++) {
                uint32_t bh[4];
                uint32_t koff = (uint32_t)(ng * 16 + b_row) * QPITCH + ks * 32 + b_kh * 16;
                ldm4(bh, st + OFF_K + koff);
                mma16816h(s[2 * ng],     qf[ks], &bh[0]);
                mma16816h(s[2 * ng + 1], qf[ks], &bh[2]);
            }
        }

        // ---- causal mask (diagonal tile only) ----
        if (kt == qt) {
#pragma unroll
            for (int nf = 0; nf < 16; nf++) {
                int c0 = kt * 128 + nf * 8 + ec2;
                if (c0     > row0)     s[nf][0] = -1e30f;
                if (c0 + 1 > row0)     s[nf][1] = -1e30f;
                if (c0     > row0 + 8) s[nf][2] = -1e30f;
                if (c0 + 1 > row0 + 8) s[nf][3] = -1e30f;
            }
        }

        // ---- streaming softmax (quad-local) ----
        float mx0 = -1e30f, mx1 = -1e30f;
#pragma unroll
        for (int nf = 0; nf < 16; nf++) {
            mx0 = fmaxf(mx0, fmaxf(s[nf][0], s[nf][1]));
            mx1 = fmaxf(mx1, fmaxf(s[nf][2], s[nf][3]));
        }
        mx0 = fmaxf(mx0, __shfl_xor_sync(0xffffffffu, mx0, 1));
        mx0 = fmaxf(mx0, __shfl_xor_sync(0xffffffffu, mx0, 2));
        mx1 = fmaxf(mx1, __shfl_xor_sync(0xffffffffu, mx1, 1));
        mx1 = fmaxf(mx1, __shfl_xor_sync(0xffffffffu, mx1, 2));
        float mn0 = fmaxf(m0, mx0), mn1 = fmaxf(m1, mx1);
        float al0 = __expf(m0 - mn0), al1 = __expf(m1 - mn1);
        m0 = mn0; m1 = mn1;

        float ls0 = 0.f, ls1 = 0.f;
        uint32_t pa[8][4];
#pragma unroll
        for (int nf = 0; nf < 16; nf++) {
            float p0 = __expf(s[nf][0] - mn0);
            float p1 = __expf(s[nf][1] - mn0);
            float p2 = __expf(s[nf][2] - mn1);
            float p3 = __expf(s[nf][3] - mn1);
            ls0 += p0 + p1; ls1 += p2 + p3;
            int q = nf >> 1, base = (nf & 1) * 2;
            pa[q][base]     = pack_h2(p0, p1);
            pa[q][base + 1] = pack_h2(p2, p3);
        }
        ls0 += __shfl_xor_sync(0xffffffffu, ls0, 1);
        ls0 += __shfl_xor_sync(0xffffffffu, ls0, 2);
        ls1 += __shfl_xor_sync(0xffffffffu, ls1, 1);
        ls1 += __shfl_xor_sync(0xffffffffu, ls1, 2);
        l0 = l0 * al0 + ls0;
        l1 = l1 * al1 + ls1;
#pragma unroll
        for (int df = 0; df < 16; df++) {
            O[df][0] *= al0; O[df][1] *= al0;
            O[df][2] *= al1; O[df][3] *= al1;
        }

        // ---- O += P V over 128 k-rows ----
#pragma unroll
        for (int q = 0; q < 8; q++) {
#pragma unroll
            for (int ng = 0; ng < 8; ng++) {
                uint32_t vh[4];
                uint32_t voff = (uint32_t)(ng * 16 + b_row) * QPITCH + q * 32 + b_kh * 16;
                ldm4(vh, st + OFF_V + voff);
                mma16816h(O[2 * ng],     pa[q], &vh[0]);
                mma16816h(O[2 * ng + 1], pa[q], &vh[2]);
            }
        }
        __syncthreads();
    }

    float il0 = 1.0f / l0, il1 = 1.0f / l1;
    size_t r0 = (size_t)(b * T_ + q0 + w * 16 + er);
    __half* y0 = Ys + r0 * K_ + h * HD_;
    __half* y1 = Ys + (r0 + 8) * K_ + h * HD_;
#pragma unroll
    for (int nf = 0; nf < 16; nf++) {
        int co = nf * 8 + ec2;
        *(uint32_t*)(y0 + co) = pack_h2(O[nf][0] * il0, O[nf][1] * il0);
        *(uint32_t*)(y1 + co) = pack_h2(O[nf][2] * il1, O[nf][3] * il1);
    }
}

// ---------------- launch ----------------
extern "C" void kernel_launch(void* const* d_in, const int* in_sizes, int n_in,
                              void* d_out, int out_size)
{
    const float* x      = (const float*)d_in[0];
    const float* w_qkv  = (const float*)d_in[1];
    const float* w_proj = (const float*)d_in[2];
    const float* qw     = (const float*)d_in[3];
    const float* kw     = (const float*)d_in[4];
    const float* fcos   = (const float*)d_in[5];
    const float* fsin   = (const float*)d_in[6];
    float* out = (float*)d_out;

    __half *p_xs, *p_wqkvs, *p_wprojs, *p_ysh, *p_qs, *p_ks, *p_vt;
    cudaGetSymbolAddress((void**)&p_xs,     g_xs);
    cudaGetSymbolAddress((void**)&p_wqkvs,  g_wqkvs);
    cudaGetSymbolAddress((void**)&p_wprojs, g_wprojs);
    cudaGetSymbolAddress((void**)&p_ysh,    g_ysh);
    cudaGetSymbolAddress((void**)&p_qs,     g_qs);
    cudaGetSymbolAddress((void**)&p_ks,     g_ks);
    cudaGetSymbolAddress((void**)&p_vt,     g_vt);

    cudaFuncSetAttribute(gemm_qkv, cudaFuncAttributeMaxDynamicSharedMemorySize, GEMM_SMEM);
    cudaFuncSetAttribute(gemm_mma, cudaFuncAttributeMaxDynamicSharedMemorySize, GEMM_SMEM);
    cudaFuncSetAttribute(flash_mma, cudaFuncAttributeMaxDynamicSharedMemorySize, FA_SMEM);

    // 0) fp16 conversions (single kernel)
    conv_all<<<(CTOT + 255) / 256, 256>>>(x, w_qkv, w_proj, p_xs, p_wqkvs, p_wprojs);

    // 1) fused qkv GEMM + RoPE + RMSNorm + V-transpose -> Q,K,V^T fp16
    gemm_qkv<<<dim3(QKVD_ / 256, BT_ / 128), 256, GEMM_SMEM>>>(
        p_xs, p_wqkvs, qw, kw, fcos, fsin, p_qs, p_ks, p_vt);

    // 2) causal flash attention (fp16 tensor cores, KT=128) -> y fp16
    flash_mma<<<dim3(T_ / 128, NH_, B_), 256, FA_SMEM>>>(p_qs, p_ks, p_vt, p_ysh);

    // 3) out = y @ w_proj^T
    gemm_mma<<<dim3(C_ / 256, BT_ / 128), 256, GEMM_SMEM>>>(p_ysh, p_wprojs, out, C_);
}